// round 14
// baseline (speedup 1.0000x reference)
#include <cuda_runtime.h>
#include <cstdint>

#define NB 64
#define NS 512
#define NH 768
#define NL 9
#define NCH 8
#define CHS 64

typedef unsigned long long ull;

// scratch (static device globals — no allocation)
__device__ float g_feats[NB * NS * NL];
__device__ float g_M[NB * NCH * 81];     // per-(batch,chunk) 9x9 log transfer matrices
__device__ int   g_cnt[NB];              // chunk-completion counters (self-resetting)

__device__ __forceinline__ ull ffma2(ull a, ull b, ull c) {
    ull d;
    asm("fma.rn.f32x2 %0, %1, %2, %3;" : "=l"(d) : "l"(a), "l"(b), "l"(c));
    return d;
}

// ---------------------------------------------------------------------------
// Phase 1: feats[tok][l] = hidden[tok] . W[l] + b[l]
// Split-K: 8-lane group per token (4 tokens/warp), lane owns 96 h-dims.
// acc = 9 packed f32x2 (18 regs) -> ~45 regs total -> 4 CTAs/SM (2x occupancy
// vs R12) so DRAM latency is finally covered. W via __ldg: all 4 groups read
// the same addresses -> 1 line/wavefront, W stays hot in L1 (27.6 KB).
// No smem, no block syncs. Also zeroes out[0] for the downstream atomic mean.
// ---------------------------------------------------------------------------
__global__ __launch_bounds__(256, 4) void gemm_kernel(
    const float* __restrict__ hidden, const float* __restrict__ W,
    const float* __restrict__ bias, float* __restrict__ out)
{
    int tid  = threadIdx.x;
    int lane = tid & 31;
    int gw   = (blockIdx.x * 256 + tid) >> 5;    // global warp 0..8191
    int g    = lane >> 3;                        // token group 0..3
    int lp   = lane & 7;                         // lane-in-group 0..7
    int tok  = gw * 4 + g;

    if (blockIdx.x == 0 && tid == 0) out[0] = 0.0f;

    const float* hrow = hidden + (size_t)tok * NH + lp * 4;

    ull acc[NL];
#pragma unroll
    for (int l = 0; l < NL; l++) acc[l] = 0ull;

    ulonglong2 hv = __ldg((const ulonglong2*)hrow);          // i = 0
#pragma unroll 4
    for (int i = 0; i < 24; i++) {
        ulonglong2 hvn;
        if (i < 23) hvn = __ldg((const ulonglong2*)(hrow + (i + 1) * 32));
        const float* wb = W + i * 32 + lp * 4;
#pragma unroll
        for (int l = 0; l < NL; l++) {
            ulonglong2 wv = __ldg((const ulonglong2*)(wb + l * NH));
            acc[l] = ffma2(hv.x, wv.x, acc[l]);
            acc[l] = ffma2(hv.y, wv.y, acc[l]);
        }
        hv = hvn;
    }

    // reduce over the 8-lane group (xor offsets 4,2,1), leader writes 9 floats
    float res[NL];
#pragma unroll
    for (int l = 0; l < NL; l++) {
        float lo, hi;
        asm("mov.b64 {%0, %1}, %2;" : "=f"(lo), "=f"(hi) : "l"(acc[l]));
        float v = lo + hi;
        v += __shfl_xor_sync(0xffffffffu, v, 4);
        v += __shfl_xor_sync(0xffffffffu, v, 2);
        v += __shfl_xor_sync(0xffffffffu, v, 1);
        res[l] = v;
    }
    if (lp == 0) {
        float* o = g_feats + (size_t)tok * NL;
#pragma unroll
        for (int l = 0; l < NL; l++) o[l] = res[l] + __ldg(bias + l);
    }
}

// ---------------------------------------------------------------------------
// dtype-agnostic mask length (prefix mask; 1-byte bool or 4-byte int/float).
// ---------------------------------------------------------------------------
__device__ __forceinline__ int mask_len_warp(const unsigned char* mask, int b, int lane) {
    int c = 0;
    if (mask[1] != 0) {
        const uint4* mp = (const uint4*)(mask + (size_t)b * NS);
        uint4 mv = mp[lane];
        c = __dp4a((int)mv.x, 0x01010101, c);
        c = __dp4a((int)mv.y, 0x01010101, c);
        c = __dp4a((int)mv.z, 0x01010101, c);
        c = __dp4a((int)mv.w, 0x01010101, c);
    } else {
        const uint4* mp = (const uint4*)((const uint32_t*)mask + (size_t)b * NS);
#pragma unroll
        for (int k = 0; k < 4; k++) {
            uint4 mv = mp[lane * 4 + k];
            c += (mv.x != 0u) + (mv.y != 0u) + (mv.z != 0u) + (mv.w != 0u);
        }
    }
#pragma unroll
    for (int o = 16; o > 0; o >>= 1) c += __shfl_xor_sync(0xffffffffu, c, o);
    return c;
}

// ---------------------------------------------------------------------------
// Phase 2 (fused): block (b,c) computes its 9x9 chunk transfer matrix
// (3 warps, basis rows in exp domain, renorm every 8 steps). The 8th
// finisher block per batch folds alpha0 through the matrices (warp 0),
// computes the gold-path score (warp 1), and atomicAdds the mean NLL.
// ---------------------------------------------------------------------------
__global__ __launch_bounds__(96) void crf_kernel(
    const float* __restrict__ startv, const float* __restrict__ endv,
    const float* __restrict__ trans, const int* __restrict__ labels,
    const unsigned char* __restrict__ mask, float* __restrict__ out)
{
    __shared__ float s_ef[CHS + 1][NL];          // exp(feats) window
    __shared__ float s_M[NCH][81];
    __shared__ float s_score, s_logden;
    __shared__ int   s_last;

    int bx   = blockIdx.x;
    int b    = bx >> 3, c = bx & 7;
    int tid  = threadIdx.x;
    int lane = tid & 31;
    int wid  = tid >> 5;
    int t0   = c * CHS;

    const float* fb = g_feats + (size_t)b * NS * NL;

    for (int i = tid; i < (CHS + 1) * NL; i += 96) {
        int t = min(t0 + i / NL, NS - 1);
        s_ef[i / NL][i % NL] = __expf(fb[t * NL + i % NL]);
    }
    int len = mask_len_warp(mask, b, lane);
    __syncthreads();

    {
        int jl = lane < 27 ? lane : 26;          // lanes 27..31 mirror lane 26
        int rl = jl / 9, j = jl % 9;
        int r  = wid * 3 + rl;
        int base = rl * 9;

        float Ecol[NL];
#pragma unroll
        for (int i = 0; i < NL; i++) Ecol[i] = __expf(__ldg(trans + i * NL + j));

        float q = (j == r) ? 1.0f : 0.0f;        // basis row r, exp domain
        float C = 0.0f;

        int tstart = (c == 0) ? 1 : t0;
        int tend   = min(t0 + CHS, len);

        float eft = s_ef[max(tstart - t0, 0)][j];
        for (int t = tstart; t < tend; t++) {
            float efn = s_ef[t + 1 - t0][j];
            float q0 = __shfl_sync(0xffffffffu, q, base + 0);
            float q1 = __shfl_sync(0xffffffffu, q, base + 1);
            float q2 = __shfl_sync(0xffffffffu, q, base + 2);
            float q3 = __shfl_sync(0xffffffffu, q, base + 3);
            float q4 = __shfl_sync(0xffffffffu, q, base + 4);
            float q5 = __shfl_sync(0xffffffffu, q, base + 5);
            float q6 = __shfl_sync(0xffffffffu, q, base + 6);
            float q7 = __shfl_sync(0xffffffffu, q, base + 7);
            float q8 = __shfl_sync(0xffffffffu, q, base + 8);
            float p  = ((q0*Ecol[0] + q1*Ecol[1]) + (q2*Ecol[2] + q3*Ecol[3]))
                     + ((q4*Ecol[4] + q5*Ecol[5]) + (q6*Ecol[6] + q7*Ecol[7]))
                     + q8*Ecol[8];
            float qn = p * eft;
            eft = efn;
            if ((t & 7) == 7) {                  // renorm (q0 > 0 after >=1 step)
                C += __logf(q0);
                qn *= __fdividef(1.0f, q0);
            }
            q = qn;
        }
        if (lane < 27)
            g_M[bx * 81 + r * NL + j] = C + __logf(q);
    }

    // completion handshake: 8th finisher per batch does the combine
    __threadfence();
    __syncthreads();
    if (tid == 0) s_last = (atomicAdd(&g_cnt[b], 1) == NCH - 1);
    __syncthreads();
    if (!s_last) return;

    for (int i = tid; i < NCH * 81; i += 96)
        s_M[i / 81][i % 81] = g_M[b * NCH * 81 + i];
    __syncthreads();

    if (wid == 0) {
        int j = lane < 9 ? lane : 8;
        float v = __ldg(startv + j) + fb[j];     // log alpha_0
        for (int cc = 0; cc < NCH; cc++) {
            if (cc * CHS < len) {
                float x0 = __shfl_sync(0xffffffffu, v, 0) + s_M[cc][0*NL + j];
                float x1 = __shfl_sync(0xffffffffu, v, 1) + s_M[cc][1*NL + j];
                float x2 = __shfl_sync(0xffffffffu, v, 2) + s_M[cc][2*NL + j];
                float x3 = __shfl_sync(0xffffffffu, v, 3) + s_M[cc][3*NL + j];
                float x4 = __shfl_sync(0xffffffffu, v, 4) + s_M[cc][4*NL + j];
                float x5 = __shfl_sync(0xffffffffu, v, 5) + s_M[cc][5*NL + j];
                float x6 = __shfl_sync(0xffffffffu, v, 6) + s_M[cc][6*NL + j];
                float x7 = __shfl_sync(0xffffffffu, v, 7) + s_M[cc][7*NL + j];
                float x8 = __shfl_sync(0xffffffffu, v, 8) + s_M[cc][8*NL + j];
                float m = fmaxf(fmaxf(fmaxf(fmaxf(x0,x1),fmaxf(x2,x3)),
                                       fmaxf(fmaxf(x4,x5),fmaxf(x6,x7))), x8);
                float s = ((__expf(x0-m)+__expf(x1-m)) + (__expf(x2-m)+__expf(x3-m)))
                        + ((__expf(x4-m)+__expf(x5-m)) + (__expf(x6-m)+__expf(x7-m)))
                        + __expf(x8-m);
                v = m + __logf(s);
            }
        }
        float t = (lane < 9) ? v + __ldg(endv + j) : -3.0e38f;
        float m = t;
#pragma unroll
        for (int o = 16; o > 0; o >>= 1) m = fmaxf(m, __shfl_xor_sync(0xffffffffu, m, o));
        float e = (lane < 9) ? __expf(t - m) : 0.0f;
#pragma unroll
        for (int o = 16; o > 0; o >>= 1) e += __shfl_xor_sync(0xffffffffu, e, o);
        if (lane == 0) s_logden = m + __logf(e);
    } else if (wid == 1) {
        // gold-path score
        const int* lab = labels + (size_t)b * NS;
        float sc = 0.0f;
        for (int t = lane; t < NS; t += 32) {
            if (t >= 1 && t < len) {
                int lp = __ldg(lab + t - 1);
                int lc = __ldg(lab + t);
                sc += __ldg(trans + lp * NL + lc) + fb[t * NL + lc];
            }
        }
        if (lane == 0) {
            int l0 = __ldg(lab);
            sc += __ldg(startv + l0) + fb[l0];
            sc += __ldg(endv + __ldg(lab + len - 1));
        }
#pragma unroll
        for (int o = 16; o > 0; o >>= 1)
            sc += __shfl_xor_sync(0xffffffffu, sc, o);
        if (lane == 0) s_score = sc;
    }
    __syncthreads();
    if (tid == 0) {
        g_cnt[b] = 0;                            // reset for next graph replay
        atomicAdd(out, (s_logden - s_score) * (1.0f / NB));
    }
}

extern "C" void kernel_launch(void* const* d_in, const int* in_sizes, int n_in,
                              void* d_out, int out_size) {
    const float*         hidden = (const float*)d_in[0];
    const float*         W      = (const float*)d_in[1];
    const float*         bias   = (const float*)d_in[2];
    const float*         startv = (const float*)d_in[3];
    const float*         endv   = (const float*)d_in[4];
    const float*         trans  = (const float*)d_in[5];
    const int*           labels = (const int*)d_in[6];
    const unsigned char* mask   = (const unsigned char*)d_in[7];
    float*               out    = (float*)d_out;

    gemm_kernel<<<NB * NS / 32, 256>>>(hidden, W, bias, out);
    crf_kernel<<<NB * NCH, 96>>>(startv, endv, trans, labels, mask, out);
}